// round 11
// baseline (speedup 1.0000x reference)
#include <cuda_runtime.h>
#include <cuda_fp16.h>
#include <cstdint>

// Problem constants
#define B_  4
#define C_  256
#define H_  64
#define W_  64
#define CO_ 256
#define S_  4096
#define KT_ 9

#define BN  128          // positions per CTA
#define CKC 64           // channels per K-chunk
#define NCH 36           // chunks = 9 taps * 4
#define NTH 256          // 8 warps, warp tile 64m x 64n
#define ASTRH 72         // A row stride in halves (64 + 8 pad)
#define BSTRH 72

// Dynamic smem map (bytes)
#define ASTAGE  36864    // 256*72*2
#define BSTAGE  18432    // 128*72*2
#define SM_A    0        // 2 stages -> 73728
#define SM_B    73728    // 2 stages -> 36864
#define SM_META 110592   // MetaH[128] = 4096
#define SMEM_SZ 114688

// Scratch
__device__ __align__(256) half g_xth[B_ * S_ * C_];        // x -> [B, HW, C] fp16
__device__ __align__(256) half g_wAh[NCH * CO_ * ASTRH];   // prepped fp16 A images

struct MetaH { uint32_t w0, w1, w2, w3; int i0, i1, i2, i3; };  // half2 weights

// ---------------------------------------------------------------------------
// Helpers
// ---------------------------------------------------------------------------
__device__ __forceinline__ uint32_t smem_u32(const void* p) {
    uint32_t a;
    asm("{ .reg .u64 t; cvta.to.shared.u64 t, %1; cvt.u32.u64 %0, t; }" : "=r"(a) : "l"(p));
    return a;
}
__device__ __forceinline__ void ldsm_x4(uint32_t& r0, uint32_t& r1, uint32_t& r2, uint32_t& r3,
                                        uint32_t addr) {
    asm volatile("ldmatrix.sync.aligned.m8n8.x4.shared.b16 {%0,%1,%2,%3}, [%4];"
                 : "=r"(r0), "=r"(r1), "=r"(r2), "=r"(r3) : "r"(addr));
}
__device__ __forceinline__ void mma_fp16(float d[4], uint32_t a0, uint32_t a1,
                                         uint32_t a2, uint32_t a3,
                                         uint32_t b0, uint32_t b1) {
    asm volatile(
        "mma.sync.aligned.m16n8k16.row.col.f32.f16.f16.f32 "
        "{%0,%1,%2,%3}, {%4,%5,%6,%7}, {%8,%9}, {%0,%1,%2,%3};"
        : "+f"(d[0]), "+f"(d[1]), "+f"(d[2]), "+f"(d[3])
        : "r"(a0), "r"(a1), "r"(a2), "r"(a3), "r"(b0), "r"(b1));
}
#define CP_ASYNC16(dst, src) \
    asm volatile("cp.async.ca.shared.global [%0], [%1], 16;" :: "r"(dst), "l"(src))
#define CP_COMMIT() asm volatile("cp.async.commit_group;" ::: "memory")
#define CP_WAIT0()  asm volatile("cp.async.wait_group 0;" ::: "memory")

// ---------------------------------------------------------------------------
// Transpose + fp16 convert: [B, C, HW] -> [B, HW, C] half
// ---------------------------------------------------------------------------
__global__ void transpose_x_kernel(const float* __restrict__ x) {
    __shared__ float tile[32][33];
    const int b  = blockIdx.z;
    const int sb = blockIdx.x * 32;
    const int cb = blockIdx.y * 32;
    const int tx = threadIdx.x;
    const int ty = threadIdx.y;
    const float* xb = x + (size_t)b * C_ * S_;
#pragma unroll
    for (int i = 0; i < 32; i += 8)
        tile[ty + i][tx] = xb[(size_t)(cb + ty + i) * S_ + sb + tx];
    __syncthreads();
    half* xtb = g_xth + (size_t)b * S_ * C_;
#pragma unroll
    for (int i = 0; i < 32; i += 8)
        xtb[(size_t)(sb + ty + i) * C_ + cb + tx] = __float2half(tile[tx][ty + i]);
}

// ---------------------------------------------------------------------------
// Prep weights: fp16 A images [q][co][72] (64 channels + 8 pad)
// ---------------------------------------------------------------------------
__global__ void prep_w_kernel(const float* __restrict__ w) {
    int idx = blockIdx.x * blockDim.x + threadIdx.x;
    if (idx >= NCH * CO_ * ASTRH) return;
    int cc = idx % ASTRH;
    int co = (idx / ASTRH) & 255;
    int q  = idx / (ASTRH * CO_);
    int k  = q >> 2;
    int c  = (q & 3) * CKC + cc;
    half v = __float2half(0.0f);
    if (cc < CKC) v = __float2half(w[((size_t)co * C_ + c) * KT_ + k]);
    g_wAh[idx] = v;
}

// ---------------------------------------------------------------------------
// Main: fp16 mma.sync implicit GEMM, 8 warps, warp tile 64m x 64n
// ---------------------------------------------------------------------------
__global__ __launch_bounds__(NTH, 1) void deform_fp16_kernel(
    const float* __restrict__ offset, float* __restrict__ out)
{
    extern __shared__ __align__(1024) char smem[];
    const uint32_t sbase = smem_u32(smem);
    MetaH* metap = (MetaH*)(smem + SM_META);

    const int tid  = threadIdx.x;
    const int lane = tid & 31;
    const int warp = tid >> 5;          // 0..7
    const int b    = blockIdx.y;
    const int p0   = blockIdx.x * BN;

    const int g   = lane >> 2;
    const int tig = lane & 3;
    const int wm  = (warp >> 1) * 64;   // 4 m groups
    const int wn  = (warp & 1) * 64;    // 2 n groups

    // Gather mapping: 8 threads per position-line; each thread covers 4 positions
    const int gpl = tid >> 3;           // 0..31 (positions gpl, +32, +64, +96)
    const int gch = (tid & 7) * 8;      // 16B slot within the 128B line

    const half*  xthb = g_xth + (size_t)b * S_ * C_;
    const float* offb = offset + (size_t)b * (2 * KT_) * S_;

    float acc[4][8][4];
#pragma unroll
    for (int i = 0; i < 4; ++i)
#pragma unroll
        for (int j = 0; j < 8; ++j)
#pragma unroll
            for (int r = 0; r < 4; ++r) acc[i][j][r] = 0.0f;

    const uint32_t aRowOff = (uint32_t)(wm + (lane & 7) + ((lane >> 3) & 1) * 8) * (ASTRH * 2)
                           + (lane >> 4) * 16;
    const uint32_t bRowOff = (uint32_t)(wn + (lane & 7)) * (BSTRH * 2)
                           + (lane >> 3) * 16;

    auto write_meta = [&](int k) {
        if (tid < BN) {
            const int p  = p0 + tid;
            const int ho = p >> 6;
            const int wo = p & 63;
            const float sy = offb[(size_t)(2 * k) * S_ + p]     + (float)(ho - 1 + k / 3);
            const float sx = offb[(size_t)(2 * k + 1) * S_ + p] + (float)(wo - 1 + k % 3);
            const float y0f = floorf(sy), x0f = floorf(sx);
            const float dy = sy - y0f,  dx = sx - x0f;
            const int y0 = (int)y0f, x0 = (int)x0f;
            const int y1 = y0 + 1,   x1 = x0 + 1;
            const bool vy0 = (y0 >= 0) && (y0 < H_);
            const bool vy1 = (y1 >= 0) && (y1 < H_);
            const bool vx0 = (x0 >= 0) && (x0 < W_);
            const bool vx1 = (x1 >= 0) && (x1 < W_);
            const int cy0 = min(max(y0, 0), H_ - 1), cy1 = min(max(y1, 0), H_ - 1);
            const int cx0 = min(max(x0, 0), W_ - 1), cx1 = min(max(x1, 0), W_ - 1);
            MetaH mm;
            half2 h;
            h = __float2half2_rn((1.0f - dy) * (1.0f - dx) * ((vy0 && vx0) ? 1.0f : 0.0f));
            mm.w0 = *(uint32_t*)&h;
            h = __float2half2_rn((1.0f - dy) * dx          * ((vy0 && vx1) ? 1.0f : 0.0f));
            mm.w1 = *(uint32_t*)&h;
            h = __float2half2_rn(dy * (1.0f - dx)          * ((vy1 && vx0) ? 1.0f : 0.0f));
            mm.w2 = *(uint32_t*)&h;
            h = __float2half2_rn(dy * dx                   * ((vy1 && vx1) ? 1.0f : 0.0f));
            mm.w3 = *(uint32_t*)&h;
            mm.i0 = (cy0 * W_ + cx0) * C_;
            mm.i1 = (cy0 * W_ + cx1) * C_;
            mm.i2 = (cy1 * W_ + cx0) * C_;
            mm.i3 = (cy1 * W_ + cx1) * C_;
            metap[tid] = mm;
        }
    };

    auto issue_A = [&](int q) {
        const char* asrc = (const char*)g_wAh + (size_t)q * ASTAGE;
        const uint32_t adst = sbase + SM_A + ((q & 1) * ASTAGE);
#pragma unroll
        for (int i = 0; i < 9; ++i) {
            int idx = i * NTH + tid;
            CP_ASYNC16(adst + idx * 16, asrc + idx * 16);
        }
        CP_COMMIT();
    };

    auto combine = [&](const MetaH& m, const uint4& u0, const uint4& u1,
                       const uint4& u2, const uint4& u3, uint32_t cvo[4]) {
        const half2 W0 = *(const half2*)&m.w0;
        const half2 W1 = *(const half2*)&m.w1;
        const half2 W2 = *(const half2*)&m.w2;
        const half2 W3 = *(const half2*)&m.w3;
        const half2* h0 = (const half2*)&u0;
        const half2* h1 = (const half2*)&u1;
        const half2* h2 = (const half2*)&u2;
        const half2* h3 = (const half2*)&u3;
#pragma unroll
        for (int j = 0; j < 4; ++j) {
            half2 t0 = __hfma2(W1, h1[j], __hmul2(W0, h0[j]));
            half2 t1 = __hfma2(W3, h3[j], __hmul2(W2, h2[j]));
            half2 r  = __hadd2(t0, t1);
            cvo[j] = *(uint32_t*)&r;
        }
    };

    uint32_t cvv[4][4];   // 4 position groups x 4 regs
    auto do_loads = [&](int q) {
        issue_A(q);
        const half* base = xthb + (q & 3) * CKC + gch;
#pragma unroll
        for (int pg = 0; pg < 4; ++pg) {
            const MetaH m = metap[gpl + pg * 32];
            const uint4 u0 = *(const uint4*)(base + m.i0);
            const uint4 u1 = *(const uint4*)(base + m.i1);
            const uint4 u2 = *(const uint4*)(base + m.i2);
            const uint4 u3 = *(const uint4*)(base + m.i3);
            combine(m, u0, u1, u2, u3, cvv[pg]);
        }
    };

    // ---- prologue ----
    write_meta(0);
    __syncthreads();
    do_loads(0);

#pragma unroll 1
    for (int q = 0; q < NCH; ++q) {
        const int s = q & 1;

        // store B columns for chunk q
        {
            char* bp = smem + SM_B + s * BSTAGE + gch * 2;
#pragma unroll
            for (int pg = 0; pg < 4; ++pg)
                *(uint4*)(bp + (uint32_t)(gpl + pg * 32) * (BSTRH * 2)) =
                    make_uint4(cvv[pg][0], cvv[pg][1], cvv[pg][2], cvv[pg][3]);
        }

        CP_WAIT0();          // A image for chunk q complete
        __syncthreads();

        if (((q + 1) & 3) == 0 && q + 1 < NCH) {
            write_meta((q + 1) >> 2);
            __syncthreads();
        }

        if (q + 1 < NCH) do_loads(q + 1);   // overlaps mma below

        const uint32_t aBase = sbase + SM_A + s * ASTAGE + aRowOff;
        const uint32_t bBase = sbase + SM_B + s * BSTAGE + bRowOff;

#pragma unroll
        for (int h = 0; h < 2; ++h) {
            uint32_t bf[8][4];
#pragma unroll
            for (int nt = 0; nt < 8; ++nt)
                ldsm_x4(bf[nt][0], bf[nt][1], bf[nt][2], bf[nt][3],
                        bBase + (uint32_t)nt * 8 * (BSTRH * 2) + h * 64);
#pragma unroll
            for (int ks = 0; ks < 2; ++ks) {
#pragma unroll
                for (int mt = 0; mt < 4; ++mt) {
                    uint32_t a0, a1, a2, a3;
                    ldsm_x4(a0, a1, a2, a3,
                            aBase + (uint32_t)mt * 16 * (ASTRH * 2) + h * 64 + ks * 32);
#pragma unroll
                    for (int nt = 0; nt < 8; ++nt)
                        mma_fp16(acc[mt][nt], a0, a1, a2, a3,
                                 bf[nt][2 * ks], bf[nt][2 * ks + 1]);
                }
            }
        }
    }

    // ---- epilogue ----
    float* ob = out + (size_t)b * CO_ * S_;
#pragma unroll
    for (int mt = 0; mt < 4; ++mt) {
#pragma unroll
        for (int nt = 0; nt < 8; ++nt) {
            const int crow = wm + mt * 16 + g;
            const int pcol = p0 + wn + nt * 8 + 2 * tig;
            *(float2*)&ob[(size_t)crow * S_ + pcol] =
                make_float2(acc[mt][nt][0], acc[mt][nt][1]);
            *(float2*)&ob[(size_t)(crow + 8) * S_ + pcol] =
                make_float2(acc[mt][nt][2], acc[mt][nt][3]);
        }
    }
}

// ---------------------------------------------------------------------------
// Launch
// ---------------------------------------------------------------------------
extern "C" void kernel_launch(void* const* d_in, const int* in_sizes, int n_in,
                              void* d_out, int out_size)
{
    (void)in_sizes; (void)n_in; (void)out_size;
    const float* x      = (const float*)d_in[0];
    const float* offset = (const float*)d_in[1];
    const float* weight = (const float*)d_in[2];
    float* out          = (float*)d_out;

    cudaFuncSetAttribute(deform_fp16_kernel,
                         cudaFuncAttributeMaxDynamicSharedMemorySize, SMEM_SZ);

    {
        dim3 grid(S_ / 32, C_ / 32, B_);
        dim3 block(32, 8);
        transpose_x_kernel<<<grid, block>>>(x);
    }
    {
        int n = NCH * CO_ * ASTRH;
        prep_w_kernel<<<(n + 255) / 256, 256>>>(weight);
    }
    {
        dim3 grid(S_ / BN, B_);
        deform_fp16_kernel<<<grid, NTH, SMEM_SZ>>>(offset, out);
    }
}

// round 12
// speedup vs baseline: 1.0120x; 1.0120x over previous
#include <cuda_runtime.h>
#include <cuda_fp16.h>
#include <cstdint>

// Problem constants
#define B_  4
#define C_  256
#define H_  64
#define W_  64
#define CO_ 256
#define S_  4096
#define KT_ 9

#define BN  128          // positions per CTA
#define CKC 128          // channels per K-chunk
#define NCH 18           // chunks = 9 taps * 2
#define NTH 512
#define ASTRH 136        // A row stride in halves (128 + 8 pad)
#define BSTRH 136

// Dynamic smem map (bytes)
#define ASTAGE  69632    // 256*136*2
#define BSTAGE  34816    // 128*136*2
#define SM_A    0        // 2 stages -> 139264
#define SM_B    139264   // 2 stages -> 69632
#define SM_META 208896   // MetaH[128] = 4096
#define SMEM_SZ 212992

// Scratch
__device__ __align__(256) half g_xth[B_ * S_ * C_];        // x -> [B, HW, C] fp16
__device__ __align__(256) half g_wAh[NCH * CO_ * ASTRH];   // prepped fp16 A images

struct MetaH { uint32_t w0, w1, w2, w3; int i0, i1, i2, i3; };  // half2 weights

// ---------------------------------------------------------------------------
// Helpers
// ---------------------------------------------------------------------------
__device__ __forceinline__ uint32_t smem_u32(const void* p) {
    uint32_t a;
    asm("{ .reg .u64 t; cvta.to.shared.u64 t, %1; cvt.u32.u64 %0, t; }" : "=r"(a) : "l"(p));
    return a;
}
__device__ __forceinline__ void ldsm_x4(uint32_t& r0, uint32_t& r1, uint32_t& r2, uint32_t& r3,
                                        uint32_t addr) {
    asm volatile("ldmatrix.sync.aligned.m8n8.x4.shared.b16 {%0,%1,%2,%3}, [%4];"
                 : "=r"(r0), "=r"(r1), "=r"(r2), "=r"(r3) : "r"(addr));
}
__device__ __forceinline__ void mma_fp16(float d[4], uint32_t a0, uint32_t a1,
                                         uint32_t a2, uint32_t a3,
                                         uint32_t b0, uint32_t b1) {
    asm volatile(
        "mma.sync.aligned.m16n8k16.row.col.f32.f16.f16.f32 "
        "{%0,%1,%2,%3}, {%4,%5,%6,%7}, {%8,%9}, {%0,%1,%2,%3};"
        : "+f"(d[0]), "+f"(d[1]), "+f"(d[2]), "+f"(d[3])
        : "r"(a0), "r"(a1), "r"(a2), "r"(a3), "r"(b0), "r"(b1));
}
#define CP_ASYNC16(dst, src) \
    asm volatile("cp.async.ca.shared.global [%0], [%1], 16;" :: "r"(dst), "l"(src))
#define CP_COMMIT() asm volatile("cp.async.commit_group;" ::: "memory")
#define CP_WAIT0()  asm volatile("cp.async.wait_group 0;" ::: "memory")

// ---------------------------------------------------------------------------
// Transpose + fp16 convert: [B, C, HW] -> [B, HW, C] half
// ---------------------------------------------------------------------------
__global__ void transpose_x_kernel(const float* __restrict__ x) {
    __shared__ float tile[32][33];
    const int b  = blockIdx.z;
    const int sb = blockIdx.x * 32;
    const int cb = blockIdx.y * 32;
    const int tx = threadIdx.x;
    const int ty = threadIdx.y;
    const float* xb = x + (size_t)b * C_ * S_;
#pragma unroll
    for (int i = 0; i < 32; i += 8)
        tile[ty + i][tx] = xb[(size_t)(cb + ty + i) * S_ + sb + tx];
    __syncthreads();
    half* xtb = g_xth + (size_t)b * S_ * C_;
#pragma unroll
    for (int i = 0; i < 32; i += 8)
        xtb[(size_t)(sb + ty + i) * C_ + cb + tx] = __float2half(tile[tx][ty + i]);
}

// ---------------------------------------------------------------------------
// Prep weights: fp16 A images [q][co][136] (128 channels + 8 pad)
// ---------------------------------------------------------------------------
__global__ void prep_w_kernel(const float* __restrict__ w) {
    int idx = blockIdx.x * blockDim.x + threadIdx.x;
    if (idx >= NCH * CO_ * ASTRH) return;
    int cc = idx % ASTRH;
    int co = (idx / ASTRH) & 255;
    int q  = idx / (ASTRH * CO_);
    int k  = q >> 1;
    int c  = (q & 1) * CKC + cc;
    half v = __float2half(0.0f);
    if (cc < CKC) v = __float2half(w[((size_t)co * C_ + c) * KT_ + k]);
    g_wAh[idx] = v;
}

// ---------------------------------------------------------------------------
// Main: fp16 mma.sync implicit GEMM, CK=128, direct-STS B build
// ---------------------------------------------------------------------------
__global__ __launch_bounds__(NTH, 1) void deform_fp16_kernel(
    const float* __restrict__ offset, float* __restrict__ out)
{
    extern __shared__ __align__(1024) char smem[];
    const uint32_t sbase = smem_u32(smem);
    MetaH* metap = (MetaH*)(smem + SM_META);

    const int tid  = threadIdx.x;
    const int lane = tid & 31;
    const int warp = tid >> 5;          // 0..15
    const int b    = blockIdx.y;
    const int p0   = blockIdx.x * BN;

    const int g   = lane >> 2;
    const int tig = lane & 3;
    const int wm  = (warp >> 2) * 64;   // warp m origin
    const int wn  = (warp & 3) * 32;    // warp n origin

    // Gather mapping: 16 threads per position-line, thread covers 4 positions
    const int gpl = tid >> 4;           // 0..31 (positions gpl, +32, +64, +96)
    const int gch = (tid & 15) * 8;     // 16B slot within the 256B row

    const half*  xthb = g_xth + (size_t)b * S_ * C_;
    const float* offb = offset + (size_t)b * (2 * KT_) * S_;

    float acc[4][4][4];
#pragma unroll
    for (int i = 0; i < 4; ++i)
#pragma unroll
        for (int j = 0; j < 4; ++j)
#pragma unroll
            for (int r = 0; r < 4; ++r) acc[i][j][r] = 0.0f;

    const uint32_t aRowOff = (uint32_t)(wm + (lane & 7) + ((lane >> 3) & 1) * 8) * (ASTRH * 2)
                           + (lane >> 4) * 16;
    const uint32_t bRowOff = (uint32_t)(wn + (lane & 7)) * (BSTRH * 2)
                           + (lane >> 3) * 16;

    auto write_meta = [&](int k) {
        if (tid < BN) {
            const int p  = p0 + tid;
            const int ho = p >> 6;
            const int wo = p & 63;
            const float sy = offb[(size_t)(2 * k) * S_ + p]     + (float)(ho - 1 + k / 3);
            const float sx = offb[(size_t)(2 * k + 1) * S_ + p] + (float)(wo - 1 + k % 3);
            const float y0f = floorf(sy), x0f = floorf(sx);
            const float dy = sy - y0f,  dx = sx - x0f;
            const int y0 = (int)y0f, x0 = (int)x0f;
            const int y1 = y0 + 1,   x1 = x0 + 1;
            const bool vy0 = (y0 >= 0) && (y0 < H_);
            const bool vy1 = (y1 >= 0) && (y1 < H_);
            const bool vx0 = (x0 >= 0) && (x0 < W_);
            const bool vx1 = (x1 >= 0) && (x1 < W_);
            const int cy0 = min(max(y0, 0), H_ - 1), cy1 = min(max(y1, 0), H_ - 1);
            const int cx0 = min(max(x0, 0), W_ - 1), cx1 = min(max(x1, 0), W_ - 1);
            MetaH mm;
            half2 h;
            h = __float2half2_rn((1.0f - dy) * (1.0f - dx) * ((vy0 && vx0) ? 1.0f : 0.0f));
            mm.w0 = *(uint32_t*)&h;
            h = __float2half2_rn((1.0f - dy) * dx          * ((vy0 && vx1) ? 1.0f : 0.0f));
            mm.w1 = *(uint32_t*)&h;
            h = __float2half2_rn(dy * (1.0f - dx)          * ((vy1 && vx0) ? 1.0f : 0.0f));
            mm.w2 = *(uint32_t*)&h;
            h = __float2half2_rn(dy * dx                   * ((vy1 && vx1) ? 1.0f : 0.0f));
            mm.w3 = *(uint32_t*)&h;
            mm.i0 = (cy0 * W_ + cx0) * C_;
            mm.i1 = (cy0 * W_ + cx1) * C_;
            mm.i2 = (cy1 * W_ + cx0) * C_;
            mm.i3 = (cy1 * W_ + cx1) * C_;
            metap[tid] = mm;
        }
    };

    auto issue_A = [&](int q) {
        const char* asrc = (const char*)g_wAh + (size_t)q * ASTAGE;
        const uint32_t adst = sbase + SM_A + ((q & 1) * ASTAGE);
#pragma unroll
        for (int i = 0; i < 9; ++i) {
            int idx = i * NTH + tid;
            if (idx < ASTAGE / 16)
                CP_ASYNC16(adst + idx * 16, asrc + idx * 16);
        }
        CP_COMMIT();
    };

    // gathers + combine + DIRECT STS into stage (q&1); frees cv registers
    auto do_loads = [&](int q) {
        issue_A(q);
        const half* base = xthb + (q & 1) * CKC + gch;
        char* bs = smem + SM_B + (q & 1) * BSTAGE + gch * 2;
#pragma unroll
        for (int pg = 0; pg < 4; ++pg) {
            const MetaH m = metap[gpl + pg * 32];
            const uint4 u0 = *(const uint4*)(base + m.i0);
            const uint4 u1 = *(const uint4*)(base + m.i1);
            const uint4 u2 = *(const uint4*)(base + m.i2);
            const uint4 u3 = *(const uint4*)(base + m.i3);
            const half2 W0 = *(const half2*)&m.w0;
            const half2 W1 = *(const half2*)&m.w1;
            const half2 W2 = *(const half2*)&m.w2;
            const half2 W3 = *(const half2*)&m.w3;
            const half2* h0 = (const half2*)&u0;
            const half2* h1 = (const half2*)&u1;
            const half2* h2 = (const half2*)&u2;
            const half2* h3 = (const half2*)&u3;
            uint32_t cv[4];
#pragma unroll
            for (int j = 0; j < 4; ++j) {
                half2 t0 = __hfma2(W1, h1[j], __hmul2(W0, h0[j]));
                half2 t1 = __hfma2(W3, h3[j], __hmul2(W2, h2[j]));
                half2 r  = __hadd2(t0, t1);
                cv[j] = *(uint32_t*)&r;
            }
            *(uint4*)(bs + (uint32_t)(gpl + pg * 32) * (BSTRH * 2)) =
                make_uint4(cv[0], cv[1], cv[2], cv[3]);
        }
    };

    // ---- prologue ----
    write_meta(0);
    __syncthreads();
    do_loads(0);
    CP_WAIT0();
    __syncthreads();

#pragma unroll 1
    for (int q = 0; q < NCH; ++q) {
        const int s = q & 1;
        const bool more = (q + 1 < NCH);

        if (more) {
            if (((q + 1) & 1) == 0) {        // new tap every 2 chunks
                write_meta((q + 1) >> 1);
                __syncthreads();
            }
            do_loads(q + 1);                 // STS into stage s^1 (free since last sync)
        }

        // ---- mma on stage s: 4 x 32-channel sub-chunks ----
        const uint32_t aBase = sbase + SM_A + s * ASTAGE + aRowOff;
        const uint32_t bBase = sbase + SM_B + s * BSTAGE + bRowOff;
#pragma unroll
        for (int h = 0; h < 4; ++h) {
            uint32_t bf[4][4];
#pragma unroll
            for (int nt = 0; nt < 4; ++nt)
                ldsm_x4(bf[nt][0], bf[nt][1], bf[nt][2], bf[nt][3],
                        bBase + (uint32_t)nt * 8 * (BSTRH * 2) + h * 64);
#pragma unroll
            for (int ks = 0; ks < 2; ++ks) {
#pragma unroll
                for (int mt = 0; mt < 4; ++mt) {
                    uint32_t a0, a1, a2, a3;
                    ldsm_x4(a0, a1, a2, a3,
                            aBase + (uint32_t)mt * 16 * (ASTRH * 2) + h * 64 + ks * 32);
#pragma unroll
                    for (int nt = 0; nt < 4; ++nt)
                        mma_fp16(acc[mt][nt], a0, a1, a2, a3,
                                 bf[nt][2 * ks], bf[nt][2 * ks + 1]);
                }
            }
        }

        if (more) {
            CP_WAIT0();                      // A(q+1) landed
            __syncthreads();                 // B(q+1) visible; stage handoff
        }
    }

    // ---- epilogue ----
    float* ob = out + (size_t)b * CO_ * S_;
#pragma unroll
    for (int mt = 0; mt < 4; ++mt) {
#pragma unroll
        for (int nt = 0; nt < 4; ++nt) {
            const int crow = wm + mt * 16 + g;
            const int pcol = p0 + wn + nt * 8 + 2 * tig;
            *(float2*)&ob[(size_t)crow * S_ + pcol] =
                make_float2(acc[mt][nt][0], acc[mt][nt][1]);
            *(float2*)&ob[(size_t)(crow + 8) * S_ + pcol] =
                make_float2(acc[mt][nt][2], acc[mt][nt][3]);
        }
    }
}

// ---------------------------------------------------------------------------
// Launch
// ---------------------------------------------------------------------------
extern "C" void kernel_launch(void* const* d_in, const int* in_sizes, int n_in,
                              void* d_out, int out_size)
{
    (void)in_sizes; (void)n_in; (void)out_size;
    const float* x      = (const float*)d_in[0];
    const float* offset = (const float*)d_in[1];
    const float* weight = (const float*)d_in[2];
    float* out          = (float*)d_out;

    cudaFuncSetAttribute(deform_fp16_kernel,
                         cudaFuncAttributeMaxDynamicSharedMemorySize, SMEM_SZ);

    {
        dim3 grid(S_ / 32, C_ / 32, B_);
        dim3 block(32, 8);
        transpose_x_kernel<<<grid, block>>>(x);
    }
    {
        int n = NCH * CO_ * ASTRH;
        prep_w_kernel<<<(n + 255) / 256, 256>>>(weight);
    }
    {
        dim3 grid(S_ / BN, B_);
        deform_fp16_kernel<<<grid, NTH, SMEM_SZ>>>(offset, out);
    }
}